// round 2
// baseline (speedup 1.0000x reference)
#include <cuda_runtime.h>

// Problem constants
#define B_    8
#define K_    64
#define L_    1024
#define CP_   32
#define AP_   8
#define G2_   9
#define CSA_  16
#define ASA_  16
#define G3_   3
#define NOC1  256          // CP*AP
#define NOC2  256          // CSA*ASA
#define K1    576          // K_*G2_  (reduction dim of conv1 as GEMM)
#define W2LEN 24           // G3*AP

// Scratch (allocation-free: device globals)
__device__ float g_yq[B_ * L_ * NOC1];      // squashed conv1 output [B, L, 256]  (8 MB)
__device__ float g_wT[K1 * NOC1];           // conv1 weights transposed [k][oc]
__device__ float g_w2T[W2LEN * NOC2];       // conv2 weights transposed [j][oc]

// ---------------------------------------------------------------------------
// Prep: transpose weights for coalesced access
// ---------------------------------------------------------------------------
__global__ void prep_kernel(const float* __restrict__ w1, const float* __restrict__ w2) {
    int idx = blockIdx.x * 256 + threadIdx.x;
    if (idx < K1 * NOC1) {
        int k = idx >> 8, oc = idx & 255;
        g_wT[idx] = w1[oc * K1 + k];
    }
    if (idx < W2LEN * NOC2) {
        int j = idx >> 8, oc = idx & 255;
        g_w2T[idx] = w2[oc * W2LEN + j];
    }
}

// ---------------------------------------------------------------------------
// Kernel 1: conv1 (implicit GEMM, 'SAME' pad) + bias + squash(per 8-group)
// Block: 32 l-positions x 256 oc, 256 threads. Each thread: 2l x 16oc in regs.
// ---------------------------------------------------------------------------
__global__ __launch_bounds__(256) void conv1_squash_kernel(
    const float* __restrict__ x, const float* __restrict__ b1)
{
    __shared__ float xs[K_][40];      // x slab: 64 ic x (32 + 8 halo)
    __shared__ float ws[8][NOC1];     // weight chunk
    __shared__ float ysh[16][NOC1];   // staging for squash (2 passes of 16 l)
    __shared__ float b1s[NOC1];

    const int b  = blockIdx.y;
    const int l0 = blockIdx.x * 32;
    const int t  = threadIdx.x;

    b1s[t] = b1[t];
    for (int i = t; i < K_ * 40; i += 256) {
        int ic = i / 40, jj = i - ic * 40;
        int l = l0 - 4 + jj;
        xs[ic][jj] = (l >= 0 && l < L_) ? x[(b * K_ + ic) * L_ + l] : 0.f;
    }

    float acc[2][16];
#pragma unroll
    for (int j = 0; j < 2; j++)
#pragma unroll
        for (int i = 0; i < 16; i++) acc[j][i] = 0.f;

    const int lg = t >> 4;   // 0..15 -> l = lg*2 + {0,1}
    const int og = t & 15;   // oc = og*4 + q*64 + r
    __syncthreads();

    for (int kc = 0; kc < K1; kc += 8) {
#pragma unroll
        for (int kk = 0; kk < 8; kk++) ws[kk][t] = g_wT[(kc + kk) * NOC1 + t];
        __syncthreads();
#pragma unroll
        for (int kk = 0; kk < 8; kk++) {
            int k  = kc + kk;
            int ic = k / 9;
            int tt = k - ic * 9;
            float xv0 = xs[ic][lg * 2 + tt];
            float xv1 = xs[ic][lg * 2 + 1 + tt];
#pragma unroll
            for (int q = 0; q < 4; q++) {
                float4 wv = *(const float4*)&ws[kk][og * 4 + q * 64];
                acc[0][q * 4 + 0] += xv0 * wv.x;
                acc[0][q * 4 + 1] += xv0 * wv.y;
                acc[0][q * 4 + 2] += xv0 * wv.z;
                acc[0][q * 4 + 3] += xv0 * wv.w;
                acc[1][q * 4 + 0] += xv1 * wv.x;
                acc[1][q * 4 + 1] += xv1 * wv.y;
                acc[1][q * 4 + 2] += xv1 * wv.z;
                acc[1][q * 4 + 3] += xv1 * wv.w;
            }
        }
        __syncthreads();
    }

    // Epilogue: two passes of 16 l. Stage y (+bias) to smem, squash, write yq.
#pragma unroll
    for (int pass = 0; pass < 2; pass++) {
        if ((lg >> 3) == pass) {
            int lb = (lg & 7) * 2;
#pragma unroll
            for (int j = 0; j < 2; j++)
#pragma unroll
                for (int q = 0; q < 4; q++)
#pragma unroll
                    for (int r = 0; r < 4; r++) {
                        int oc = og * 4 + q * 64 + r;
                        ysh[lb + j][oc] = acc[j][q * 4 + r] + b1s[oc];
                    }
        }
        __syncthreads();
        for (int g = t; g < 512; g += 256) {
            int l_loc = g >> 5, cp = g & 31;
            float4 a = *(const float4*)&ysh[l_loc][cp * 8];
            float4 c = *(const float4*)&ysh[l_loc][cp * 8 + 4];
            float sq = a.x * a.x + a.y * a.y + a.z * a.z + a.w * a.w
                     + c.x * c.x + c.y * c.y + c.z * c.z + c.w * c.w;
            float scale = sq / (1.f + sq) * rsqrtf(sq + 1e-8f);
            a.x *= scale; a.y *= scale; a.z *= scale; a.w *= scale;
            c.x *= scale; c.y *= scale; c.z *= scale; c.w *= scale;
            int l = l0 + pass * 16 + l_loc;
            float* dst = &g_yq[((size_t)(b * L_ + l)) * NOC1 + cp * 8];
            *(float4*)dst       = a;
            *(float4*)(dst + 4) = c;
        }
        __syncthreads();
    }
}

// ---------------------------------------------------------------------------
// Kernel 2: conv2 (3x8 stride-8) + bias -> V in REGISTERS, then 3-iter routing.
// One block per (b,l). Thread t = (csa, asa); V[cp] per thread (32 regs).
// ---------------------------------------------------------------------------
__global__ __launch_bounds__(256) void conv2_route_kernel(
    const float* __restrict__ b2, float* __restrict__ out)
{
    __shared__ float yq3[3][NOC1];          // rows l-1, l, l+1 (zero-padded)
    __shared__ float blog[CP_][CSA_];       // routing logits
    __shared__ float csh[CP_][CSA_];        // softmax coefficients

    const int bl = blockIdx.x;              // b*L + l
    const int l  = bl & (L_ - 1);
    const int t  = threadIdx.x;

    const float* base = g_yq + (size_t)bl * NOC1;
    yq3[1][t] = base[t];
    yq3[0][t] = (l > 0)      ? base[t - NOC1] : 0.f;
    yq3[2][t] = (l < L_ - 1) ? base[t + NOC1] : 0.f;

    float w[W2LEN];
#pragma unroll
    for (int j = 0; j < W2LEN; j++) w[j] = g_w2T[j * 256 + t];
    const float bias = b2[t];

    ((float*)blog)[t]       = 0.f;
    ((float*)blog)[t + 256] = 0.f;
    __syncthreads();

    // V[cp][csa][asa] for this thread's (csa,asa), all cp -> registers
    float V[CP_];
#pragma unroll
    for (int cp = 0; cp < CP_; cp++) {
        float acc = bias;
#pragma unroll
        for (int dh = 0; dh < 3; dh++) {
            float4 ya = *(const float4*)&yq3[dh][cp * 8];
            float4 yb = *(const float4*)&yq3[dh][cp * 8 + 4];
            acc += w[dh * 8 + 0] * ya.x;
            acc += w[dh * 8 + 1] * ya.y;
            acc += w[dh * 8 + 2] * ya.z;
            acc += w[dh * 8 + 3] * ya.w;
            acc += w[dh * 8 + 4] * yb.x;
            acc += w[dh * 8 + 5] * yb.y;
            acc += w[dh * 8 + 6] * yb.z;
            acc += w[dh * 8 + 7] * yb.w;
        }
        V[cp] = acc;
    }

    const int csa = t >> 4;
    const int asa = t & 15;
    float v = 0.f;

    for (int r = 0; r < 3; r++) {
        float s;
        if (r == 0) {
            // b = 0 -> softmax is uniform 1/16
            s = 0.f;
#pragma unroll
            for (int cp = 0; cp < CP_; cp++) s += V[cp];
            s *= (1.f / 16.f);
        } else {
            if (t < CP_) {  // one thread per cp: softmax over csa
                float mx = -1e30f;
#pragma unroll
                for (int j2 = 0; j2 < CSA_; j2++) mx = fmaxf(mx, blog[t][j2]);
                float e[CSA_];
                float sum = 0.f;
#pragma unroll
                for (int j2 = 0; j2 < CSA_; j2++) {
                    e[j2] = expf(blog[t][j2] - mx);
                    sum += e[j2];
                }
                float inv = 1.f / sum;
#pragma unroll
                for (int j2 = 0; j2 < CSA_; j2++) csh[t][j2] = e[j2] * inv;
            }
            __syncthreads();
            s = 0.f;
#pragma unroll
            for (int cp = 0; cp < CP_; cp++) s += csh[cp][csa] * V[cp];
        }

        // squash over asa (16 contiguous lanes within the warp)
        float sq = s * s;
        sq += __shfl_xor_sync(0xffffffffu, sq, 1);
        sq += __shfl_xor_sync(0xffffffffu, sq, 2);
        sq += __shfl_xor_sync(0xffffffffu, sq, 4);
        sq += __shfl_xor_sync(0xffffffffu, sq, 8);
        float scale = sq / (1.f + sq) * rsqrtf(sq + 1e-8f);
        v = s * scale;

        if (r < 2) {
            // b += a,  a[cp][csa] = sum_asa V * v  (16-lane dot via shfl)
#pragma unroll
            for (int cp = 0; cp < CP_; cp++) {
                float p = V[cp] * v;
                p += __shfl_xor_sync(0xffffffffu, p, 1);
                p += __shfl_xor_sync(0xffffffffu, p, 2);
                p += __shfl_xor_sync(0xffffffffu, p, 4);
                p += __shfl_xor_sync(0xffffffffu, p, 8);
                if (asa == 0) blog[cp][csa] += p;
            }
            __syncthreads();
        }
    }

    // out[b, l*16+csa, asa] = flat (b*L+l)*256 + t
    out[(size_t)bl * 256 + t] = v;
}

// ---------------------------------------------------------------------------
extern "C" void kernel_launch(void* const* d_in, const int* in_sizes, int n_in,
                              void* d_out, int out_size)
{
    const float* x  = (const float*)d_in[0];   // [8, 64, 1024]
    const float* w1 = (const float*)d_in[1];   // [256, 64, 9]
    const float* b1 = (const float*)d_in[2];   // [256]
    const float* w2 = (const float*)d_in[3];   // [256, 1, 3, 8]
    const float* b2 = (const float*)d_in[4];   // [256]
    float* out = (float*)d_out;                // [8, 16384, 16]

    prep_kernel<<<576, 256>>>(w1, w2);
    conv1_squash_kernel<<<dim3(L_ / 32, B_), 256>>>(x, b1);
    conv2_route_kernel<<<B_ * L_, 256>>>(b2, out);
}

// round 3
// speedup vs baseline: 1.0559x; 1.0559x over previous
#include <cuda_runtime.h>

// Problem constants
#define B_    8
#define K_    64
#define L_    1024
#define CP_   32
#define AP_   8
#define G2_   9
#define CSA_  16
#define ASA_  16
#define G3_   3
#define NOC1  256
#define NOC2  256
#define K1    576          // K_*G2_
#define W2LEN 24           // G3*AP

typedef unsigned long long ull;

// Packed fp32x2 helpers (sm_100+)
#define FFMA2(acc, a, b) asm("fma.rn.f32x2 %0, %1, %2, %0;" : "+l"(acc) : "l"(a), "l"(b))
#define PACK2(dst, f)    asm("mov.b64 %0, {%1, %1};" : "=l"(dst) : "f"(f))
#define UNPACK2(lo, hi, v) asm("mov.b64 {%0, %1}, %2;" : "=f"(lo), "=f"(hi) : "l"(v))

// Scratch (allocation-free: device globals)
__device__ float g_yq[B_ * L_ * NOC1];      // squashed conv1 output [B, L, 256]
__device__ float g_wT[K1 * NOC1];           // conv1 weights transposed [k][oc]
__device__ float g_w2T[W2LEN * NOC2];       // conv2 weights transposed [j][oc]

// ---------------------------------------------------------------------------
// Prep: transpose weights for coalesced access
// ---------------------------------------------------------------------------
__global__ void prep_kernel(const float* __restrict__ w1, const float* __restrict__ w2) {
    int idx = blockIdx.x * 256 + threadIdx.x;
    if (idx < K1 * NOC1) {
        int k = idx >> 8, oc = idx & 255;
        g_wT[idx] = w1[oc * K1 + k];
    }
    if (idx < W2LEN * NOC2) {
        int j = idx >> 8, oc = idx & 255;
        g_w2T[idx] = w2[oc * W2LEN + j];
    }
}

// ---------------------------------------------------------------------------
// Kernel 1: conv1 (implicit GEMM, 'SAME') + bias + squash. FFMA2 inner loop.
// Block: 16 l x 256 oc, 128 threads. Thread: 2l x 16oc. Grid: 512 blocks.
// ---------------------------------------------------------------------------
__global__ __launch_bounds__(128) void conv1_squash_kernel(
    const float* __restrict__ x, const float* __restrict__ b1)
{
    __shared__ float xs[K_][24];      // 64 ic x (16 + 8 halo)
    __shared__ float ws[16][NOC1];    // weight chunk (16 k rows)
    __shared__ float ysh[16][NOC1];   // staging for squash
    __shared__ float b1s[NOC1];

    const int b  = blockIdx.y;
    const int l0 = blockIdx.x * 16;
    const int t  = threadIdx.x;

    b1s[t]       = b1[t];
    b1s[t + 128] = b1[t + 128];
    for (int i = t; i < K_ * 24; i += 128) {
        int ic = i / 24, jj = i - ic * 24;
        int l = l0 - 4 + jj;
        xs[ic][jj] = (l >= 0 && l < L_) ? x[(b * K_ + ic) * L_ + l] : 0.f;
    }

    ull acc2[2][8];
#pragma unroll
    for (int j = 0; j < 2; j++)
#pragma unroll
        for (int i = 0; i < 8; i++) acc2[j][i] = 0ULL;

    const int lg = t >> 4;   // 0..7 -> l = lg*2 + {0,1}
    const int og = t & 15;   // oc = og*4 + q*64 + {0..3}
    __syncthreads();

    const float4* wT4 = (const float4*)g_wT;
    for (int kc = 0; kc < K1; kc += 16) {
        // load 16x256 weight chunk, vectorized
#pragma unroll
        for (int i = 0; i < 8; i++)
            ((float4*)ws)[t + i * 128] = wT4[kc * 64 + t + i * 128];
        __syncthreads();
#pragma unroll
        for (int kk = 0; kk < 16; kk++) {
            int k  = kc + kk;
            int ic = k / 9;
            int tt = k - ic * 9;
            float xv0 = xs[ic][lg * 2 + tt];
            float xv1 = xs[ic][lg * 2 + 1 + tt];
            ull X0, X1;
            PACK2(X0, xv0);
            PACK2(X1, xv1);
#pragma unroll
            for (int q = 0; q < 4; q++) {
                ulonglong2 wq = *(const ulonglong2*)&ws[kk][og * 4 + q * 64];
                FFMA2(acc2[0][q * 2 + 0], X0, wq.x);
                FFMA2(acc2[0][q * 2 + 1], X0, wq.y);
                FFMA2(acc2[1][q * 2 + 0], X1, wq.x);
                FFMA2(acc2[1][q * 2 + 1], X1, wq.y);
            }
        }
        __syncthreads();
    }

    // Epilogue: stage y+bias to smem, squash per 8-group, write g_yq
#pragma unroll
    for (int j = 0; j < 2; j++)
#pragma unroll
        for (int q = 0; q < 4; q++)
#pragma unroll
            for (int h = 0; h < 2; h++) {
                float lo, hi;
                UNPACK2(lo, hi, acc2[j][q * 2 + h]);
                int oc = og * 4 + q * 64 + h * 2;
                ysh[lg * 2 + j][oc]     = lo + b1s[oc];
                ysh[lg * 2 + j][oc + 1] = hi + b1s[oc + 1];
            }
    __syncthreads();
#pragma unroll
    for (int g = t; g < 512; g += 128) {
        int l_loc = g >> 5, cp = g & 31;
        float4 a = *(const float4*)&ysh[l_loc][cp * 8];
        float4 c = *(const float4*)&ysh[l_loc][cp * 8 + 4];
        float sq = a.x * a.x + a.y * a.y + a.z * a.z + a.w * a.w
                 + c.x * c.x + c.y * c.y + c.z * c.z + c.w * c.w;
        float scale = sq / (1.f + sq) * rsqrtf(sq + 1e-8f);
        a.x *= scale; a.y *= scale; a.z *= scale; a.w *= scale;
        c.x *= scale; c.y *= scale; c.z *= scale; c.w *= scale;
        int l = l0 + l_loc;
        float* dst = &g_yq[((size_t)(b * L_ + l)) * NOC1 + cp * 8];
        *(float4*)dst       = a;
        *(float4*)(dst + 4) = c;
    }
}

// ---------------------------------------------------------------------------
// Kernel 2: conv2 (FFMA2) -> V in registers, then 3-iter routing with
// butterfly multi-value reduction (30 shfl instead of 128).
// One block per (b,l). Thread t = (csa, asa).
// ---------------------------------------------------------------------------
__global__ __launch_bounds__(256) void conv2_route_kernel(
    const float* __restrict__ b2, float* __restrict__ out)
{
    __shared__ float yq3[3][NOC1];
    __shared__ float blog[CP_][CSA_];
    __shared__ float csh[CP_][CSA_];

    const int bl = blockIdx.x;
    const int l  = bl & (L_ - 1);
    const int t  = threadIdx.x;

    const float* base = g_yq + (size_t)bl * NOC1;
    yq3[1][t] = base[t];
    yq3[0][t] = (l > 0)      ? base[t - NOC1] : 0.f;
    yq3[2][t] = (l < L_ - 1) ? base[t + NOC1] : 0.f;

    // packed conv2 weights: w2p[j] = {w[2j], w[2j+1]}
    ull w2p[12];
#pragma unroll
    for (int j = 0; j < 12; j++) {
        float wl = g_w2T[(2 * j) * 256 + t];
        float wh = g_w2T[(2 * j + 1) * 256 + t];
        asm("mov.b64 %0, {%1, %2};" : "=l"(w2p[j]) : "f"(wl), "f"(wh));
    }
    const float bias = b2[t];

    ((float*)blog)[t]       = 0.f;
    ((float*)blog)[t + 256] = 0.f;
    __syncthreads();

    // V[cp] for this thread's (csa, asa)
    float V[CP_];
#pragma unroll
    for (int cp = 0; cp < CP_; cp++) {
        ull acc;
        asm("mov.b64 %0, {%1, %2};" : "=l"(acc) : "f"(bias), "f"(0.f));
#pragma unroll
        for (int dh = 0; dh < 3; dh++) {
            const ulonglong2* yp = (const ulonglong2*)&yq3[dh][cp * 8];
            ulonglong2 ya = yp[0];
            ulonglong2 yb = yp[1];
            FFMA2(acc, ya.x, w2p[dh * 4 + 0]);
            FFMA2(acc, ya.y, w2p[dh * 4 + 1]);
            FFMA2(acc, yb.x, w2p[dh * 4 + 2]);
            FFMA2(acc, yb.y, w2p[dh * 4 + 3]);
        }
        float lo, hi;
        UNPACK2(lo, hi, acc);
        V[cp] = lo + hi;
    }

    const int csa = t >> 4;
    const int asa = t & 15;
    float v = 0.f;

    for (int r = 0; r < 3; r++) {
        float s;
        if (r == 0) {
            s = 0.f;
#pragma unroll
            for (int cp = 0; cp < CP_; cp++) s += V[cp];
            s *= (1.f / 16.f);
        } else {
            if (t < CP_) {
                float mx = -1e30f;
#pragma unroll
                for (int j2 = 0; j2 < CSA_; j2++) mx = fmaxf(mx, blog[t][j2]);
                float e[CSA_];
                float sum = 0.f;
#pragma unroll
                for (int j2 = 0; j2 < CSA_; j2++) {
                    e[j2] = expf(blog[t][j2] - mx);
                    sum += e[j2];
                }
                float inv = 1.f / sum;
#pragma unroll
                for (int j2 = 0; j2 < CSA_; j2++) csh[t][j2] = e[j2] * inv;
            }
            __syncthreads();
            s = 0.f;
#pragma unroll
            for (int cp = 0; cp < CP_; cp++) s += csh[cp][csa] * V[cp];
        }

        // squash over asa (16 contiguous lanes)
        float sq = s * s;
        sq += __shfl_xor_sync(0xffffffffu, sq, 1);
        sq += __shfl_xor_sync(0xffffffffu, sq, 2);
        sq += __shfl_xor_sync(0xffffffffu, sq, 4);
        sq += __shfl_xor_sync(0xffffffffu, sq, 8);
        float scale = sq / (1.f + sq) * rsqrtf(sq + 1e-8f);
        v = s * scale;

        if (r < 2) {
            // a[cp][csa] = sum_asa V*v via multi-value butterfly.
            // After stages m=1,2,4,8, lane asa holds cp = g0*16+g1*8+g2*4+g3*2+i.
            float val[16];
            {
                bool u = (asa & 1);
#pragma unroll
                for (int i = 0; i < 16; i++) {
                    float sp = (u ? V[i] : V[16 + i]) * v;
                    float kp = (u ? V[16 + i] : V[i]) * v;
                    val[i] = kp + __shfl_xor_sync(0xffffffffu, sp, 1);
                }
            }
            {
                bool u = (asa & 2);
#pragma unroll
                for (int i = 0; i < 8; i++) {
                    float sp = u ? val[i] : val[8 + i];
                    float kp = u ? val[8 + i] : val[i];
                    val[i] = kp + __shfl_xor_sync(0xffffffffu, sp, 2);
                }
            }
            {
                bool u = (asa & 4);
#pragma unroll
                for (int i = 0; i < 4; i++) {
                    float sp = u ? val[i] : val[4 + i];
                    float kp = u ? val[4 + i] : val[i];
                    val[i] = kp + __shfl_xor_sync(0xffffffffu, sp, 4);
                }
            }
            {
                bool u = (asa & 8);
#pragma unroll
                for (int i = 0; i < 2; i++) {
                    float sp = u ? val[i] : val[2 + i];
                    float kp = u ? val[2 + i] : val[i];
                    val[i] = kp + __shfl_xor_sync(0xffffffffu, sp, 8);
                }
            }
            int c0 = ((asa & 1) << 4) | ((asa & 2) << 2) | (asa & 4) | ((asa & 8) >> 2);
            blog[c0][csa]     += val[0];
            blog[c0 + 1][csa] += val[1];
            __syncthreads();
        }
    }

    out[(size_t)bl * 256 + t] = v;
}

// ---------------------------------------------------------------------------
extern "C" void kernel_launch(void* const* d_in, const int* in_sizes, int n_in,
                              void* d_out, int out_size)
{
    const float* x  = (const float*)d_in[0];   // [8, 64, 1024]
    const float* w1 = (const float*)d_in[1];   // [256, 64, 9]
    const float* b1 = (const float*)d_in[2];   // [256]
    const float* w2 = (const float*)d_in[3];   // [256, 1, 3, 8]
    const float* b2 = (const float*)d_in[4];   // [256]
    float* out = (float*)d_out;                // [8, 16384, 16]

    prep_kernel<<<576, 256>>>(w1, w2);
    conv1_squash_kernel<<<dim3(L_ / 16, B_), 128>>>(x, b1);
    conv2_route_kernel<<<B_ * L_, 256>>>(b2, out);
}